// round 11
// baseline (speedup 1.0000x reference)
#include <cuda_runtime.h>
#include <cstdint>

#define B_SZ 4
#define T_SZ 1024
#define C_SZ 512
#define H_SZ 8
#define D_SZ 64

// Q pre-scale: 1/sqrt(64) * log2(e)  (softmax in exp2 domain)
#define Q_SCALE 0.18033688011112042f

__device__ float g_w[4][512 * 512];                // Wq*s, Wk, Wv, Wo (tf32)
__device__ float g_q[B_SZ * H_SZ * T_SZ * D_SZ];   // scaled + tf32
__device__ float g_k[B_SZ * H_SZ * T_SZ * D_SZ];   // tf32
__device__ float g_v[B_SZ * H_SZ * T_SZ * D_SZ];   // tf32
__device__ float g_att[B_SZ * T_SZ * C_SZ];

__device__ __forceinline__ uint32_t f2tf(float x) {
    uint32_t u;
    asm("cvt.rna.tf32.f32 %0, %1;" : "=r"(u) : "f"(x));
    return u;
}

__device__ __forceinline__ float ex2(float x) {
    float y;
    asm("ex2.approx.ftz.f32 %0, %1;" : "=f"(y) : "f"(x));
    return y;
}

__device__ __forceinline__ void mma_tf32(float c[4], const uint32_t a[4],
                                         uint32_t b0, uint32_t b1) {
    asm volatile(
        "mma.sync.aligned.m16n8k8.row.col.f32.tf32.tf32.f32 "
        "{%0,%1,%2,%3}, {%4,%5,%6,%7}, {%8,%9}, {%0,%1,%2,%3};\n"
        : "+f"(c[0]), "+f"(c[1]), "+f"(c[2]), "+f"(c[3])
        : "r"(a[0]), "r"(a[1]), "r"(a[2]), "r"(a[3]), "r"(b0), "r"(b1));
}

__device__ __forceinline__ void cp16(void* dst_smem, const void* src) {
    uint32_t d = (uint32_t)__cvta_generic_to_shared(dst_smem);
    asm volatile("cp.async.cg.shared.global [%0], [%1], 16;" :: "r"(d), "l"(src));
}
#define CP_COMMIT() asm volatile("cp.async.commit_group;" ::: "memory")

// ---------------------------------------------------------------------------
// Preconvert weights only: Wq*Q_SCALE, Wk, Wv, Wo -> tf32 in g_w.
// ---------------------------------------------------------------------------
#define WGRP (512 * 512 / 8)

__global__ __launch_bounds__(256) void prew_kernel(
    const float* __restrict__ Wq, const float* __restrict__ Wk,
    const float* __restrict__ Wv, const float* __restrict__ Wo)
{
    int gid = blockIdx.x * 256 + threadIdx.x;
    if (gid >= 4 * WGRP) return;
    int wi = gid / WGRP;
    int off = (gid - wi * WGRP) * 8;
    const float* src = (wi == 0) ? Wq : (wi == 1) ? Wk : (wi == 2) ? Wv : Wo;
    float s = (wi == 0) ? Q_SCALE : 1.0f;
    float4 f0 = *(const float4*)&src[off];
    float4 f1 = *(const float4*)&src[off + 4];
    *(uint4*)&g_w[wi][off] =
        make_uint4(f2tf(f0.x * s), f2tf(f0.y * s), f2tf(f0.z * s), f2tf(f0.w * s));
    *(uint4*)&g_w[wi][off + 4] =
        make_uint4(f2tf(f1.x * s), f2tf(f1.y * s), f2tf(f1.z * s), f2tf(f1.w * s));
}

// ---------------------------------------------------------------------------
// tf32 GEMM (R6 config): 128 threads, 4 warps (2x2), warp tile 64x32.
// cp.async double-buffered; weights preconverted tf32; A cvt at frag load.
// mode 0: fused QKV — grid (32, 24). mode 3: g_att @ Wo + bo — grid (32, 8).
// ---------------------------------------------------------------------------
struct GemmSmem {
    float As[2][128][36];   // raw f32 activations
    float Bs[2][32][72];    // tf32 bits (preconverted weights)
};

__global__ __launch_bounds__(128, 2) void gemm_tf32_kernel(
    const float* __restrict__ x, const float* __restrict__ cc,
    const float* __restrict__ bq, const float* __restrict__ bk,
    const float* __restrict__ bv, const float* __restrict__ bo,
    float* __restrict__ out_ext, int mode)
{
    extern __shared__ char raw[];
    GemmSmem& sm = *reinterpret_cast<GemmSmem*>(raw);

    const float* A; const float* W; const float* bias; int sel;
    int n0;
    if (mode == 0) {
        sel = blockIdx.y >> 3;
        A = (sel == 0) ? x : cc;
        W = g_w[sel];
        bias = (sel == 0) ? bq : (sel == 1) ? bk : bv;
        n0 = (blockIdx.y & 7) * 64;
    } else {
        sel = 3;
        A = g_att; W = g_w[3]; bias = bo;
        n0 = blockIdx.y * 64;
    }
    const int m0 = blockIdx.x * 128;
    const int tid = threadIdx.x;
    const int lane = tid & 31;
    const int wid = tid >> 5;
    const int g = lane >> 2;
    const int tg = lane & 3;
    const int wm = wid >> 1;
    const int wn = wid & 1;

    auto issue_tile = [&](int kt, int bufi) {
        int kb = kt * 32;
#pragma unroll
        for (int i = 0; i < 8; i++) {
            int idx = tid + i * 128;
            int r = idx >> 3;
            int kk = (idx & 7) << 2;
            cp16(&sm.As[bufi][r][kk], &A[(size_t)(m0 + r) * 512 + kb + kk]);
        }
#pragma unroll
        for (int i = 0; i < 4; i++) {
            int idx = tid + i * 128;
            int kk = idx >> 4;
            int nn = (idx & 15) << 2;
            cp16(&sm.Bs[bufi][kk][nn], &W[(size_t)(kb + kk) * 512 + n0 + nn]);
        }
        CP_COMMIT();
    };

    float c[4][4][4];
#pragma unroll
    for (int i = 0; i < 4; i++)
#pragma unroll
        for (int j = 0; j < 4; j++)
#pragma unroll
            for (int q = 0; q < 4; q++) c[i][j][q] = 0.f;

    issue_tile(0, 0);

    for (int kt = 0; kt < 16; kt++) {
        asm volatile("cp.async.wait_group 0;" ::: "memory");
        __syncthreads();
        if (kt < 15) issue_tile(kt + 1, (kt + 1) & 1);
        const float (*Af)[36] = sm.As[kt & 1];
        const float (*Bf)[72] = sm.Bs[kt & 1];

#pragma unroll
        for (int ks = 0; ks < 4; ks++) {
            int kb = ks * 8;
            uint32_t a[4][4], b[4][2];
#pragma unroll
            for (int i = 0; i < 4; i++) {
                int mr = wm * 64 + i * 16 + g;
                a[i][0] = f2tf(Af[mr][kb + tg]);
                a[i][1] = f2tf(Af[mr + 8][kb + tg]);
                a[i][2] = f2tf(Af[mr][kb + tg + 4]);
                a[i][3] = f2tf(Af[mr + 8][kb + tg + 4]);
            }
#pragma unroll
            for (int j = 0; j < 4; j++) {
                int nc = wn * 32 + j * 8 + g;
                b[j][0] = __float_as_uint(Bf[kb + tg][nc]);
                b[j][1] = __float_as_uint(Bf[kb + tg + 4][nc]);
            }
#pragma unroll
            for (int i = 0; i < 4; i++)
#pragma unroll
                for (int j = 0; j < 4; j++) mma_tf32(c[i][j], a[i], b[j][0], b[j][1]);
        }
    }

#pragma unroll
    for (int i = 0; i < 4; i++) {
        int r0 = m0 + wm * 64 + i * 16 + g;
#pragma unroll
        for (int j = 0; j < 4; j++) {
            int col0 = n0 + wn * 32 + j * 8 + tg * 2;
            float bv0 = bias[col0], bv1 = bias[col0 + 1];
            if (sel == 0) { bv0 *= Q_SCALE; bv1 *= Q_SCALE; }
            float v00 = c[i][j][0] + bv0;
            float v01 = c[i][j][1] + bv1;
            float v10 = c[i][j][2] + bv0;
            float v11 = c[i][j][3] + bv1;
            if (sel < 3) {
                v00 = __uint_as_float(f2tf(v00));
                v01 = __uint_as_float(f2tf(v01));
                v10 = __uint_as_float(f2tf(v10));
                v11 = __uint_as_float(f2tf(v11));
                float* outb = (sel == 0) ? g_q : (sel == 1) ? g_k : g_v;
                int hh = col0 >> 6;
                int d = col0 & 63;
                {
                    int bb = r0 >> 10, t = r0 & 1023;
                    size_t base = ((((size_t)bb * H_SZ + hh) << 10) + t) * D_SZ + d;
                    *(float2*)&outb[base] = make_float2(v00, v01);
                }
                {
                    int r1 = r0 + 8;
                    int bb = r1 >> 10, t = r1 & 1023;
                    size_t base = ((((size_t)bb * H_SZ + hh) << 10) + t) * D_SZ + d;
                    *(float2*)&outb[base] = make_float2(v10, v11);
                }
            } else {
                *(float2*)&out_ext[(size_t)r0 * 512 + col0] = make_float2(v00, v01);
                *(float2*)&out_ext[(size_t)(r0 + 8) * 512 + col0] = make_float2(v10, v11);
            }
        }
    }
}

// ---------------------------------------------------------------------------
// Flash attention v9: shuffle-free PV. S C-fragment registers feed the PV
// A operand directly (a = {c0,c2,c1,c3}); V smem rows are permuted by
// sigma = {0,2,4,6,1,3,5,7} within each 8-row group so key/k-slot mapping
// stays consistent. No online rescale (scores bounded). 128-q CTA, m32 warps.
// ---------------------------------------------------------------------------
struct AttnSmem {
    uint32_t Qs[128][68];
    uint32_t Ks[2][64][68];
    uint32_t Vs[64][72];      // rows sigma-permuted within 8-groups
    float ek[9][64];
    float ev[9][64];
    float qe[128][12];
    float band[128][12];
};

__global__ __launch_bounds__(128, 2) void attn_kernel(const float* __restrict__ embk,
                                                      const float* __restrict__ embv)
{
    extern __shared__ char smem_raw[];
    AttnSmem& sm = *reinterpret_cast<AttnSmem*>(smem_raw);

    const int tid = threadIdx.x;
    const int lane = tid & 31;
    const int wid = tid >> 5;
    const int g = lane >> 2;
    const int tg = lane & 3;
    const int w32 = wid * 32;
    const int qt0 = blockIdx.x * 128;
    const int h = blockIdx.y;
    const int b = blockIdx.z;
    const size_t head_off = ((size_t)(b * H_SZ + h)) * T_SZ * D_SZ;
    const float* Q = g_q + head_off;
    const float* K = g_k + head_off;
    const float* V = g_v + head_off;

    for (int i = tid; i < 128 * 16; i += 128) {
        int r = i >> 4, c4 = (i & 15) << 2;
        *(uint4*)&sm.Qs[r][c4] = *(const uint4*)&Q[(size_t)(qt0 + r) * D_SZ + c4];
    }
    for (int i = tid; i < 9 * 64; i += 128) {
        sm.ek[0][i] = embk[i];
        sm.ev[0][i] = embv[i];
    }
    __syncthreads();

    for (int i = tid; i < 128 * 9; i += 128) {
        int t = i / 9, dd = i - t * 9;
        const float* qrow = (const float*)sm.Qs[t];
        float s = 0.f;
#pragma unroll
        for (int d = 0; d < 64; d += 4) {
            float4 q4 = *(const float4*)&qrow[d];
            float4 e4 = *(const float4*)&sm.ek[dd][d];
            s += q4.x * e4.x + q4.y * e4.y + q4.z * e4.z + q4.w * e4.w;
        }
        sm.qe[t][dd] = s;
    }

    // V row permutation: dest row for source key r (sigma^-1 within 8-group)
    auto vrow = [](int r) {
        return (r & 56) | ((r & 1) << 2) | ((r >> 1) & 3);
    };

#pragma unroll
    for (int i = 0; i < 8; i++) {
        int idx = tid + i * 128;
        int r = idx >> 4, c4 = (idx & 15) << 2;
        cp16(&sm.Ks[0][r][c4], &K[(size_t)r * D_SZ + c4]);
        cp16(&sm.Vs[vrow(r)][c4], &V[(size_t)r * D_SZ + c4]);
    }
    CP_COMMIT();

    float of[2][8][4];
#pragma unroll
    for (int mb = 0; mb < 2; mb++)
#pragma unroll
        for (int n = 0; n < 8; n++)
#pragma unroll
            for (int q = 0; q < 4; q++) of[mb][n][q] = 0.f;
    float lp[2][2] = {{0.f, 0.f}, {0.f, 0.f}};   // per-thread partial l sums

    for (int j = 0; j < 16; j++) {
        const int s0 = j * 64;
        if (j < 15) {
            const int s1 = s0 + 64;
#pragma unroll
            for (int i = 0; i < 8; i++) {
                int idx = tid + i * 128;
                int r = idx >> 4, c4 = (idx & 15) << 2;
                cp16(&sm.Ks[(j + 1) & 1][r][c4], &K[(size_t)(s1 + r) * D_SZ + c4]);
            }
            CP_COMMIT();
            asm volatile("cp.async.wait_group 1;" ::: "memory");
        } else {
            asm volatile("cp.async.wait_group 0;" ::: "memory");
        }
        __syncthreads();
        const int buf = j & 1;

        // ---- S = Q K^T ----
        float sc[2][8][4];
#pragma unroll
        for (int mb = 0; mb < 2; mb++)
#pragma unroll
            for (int n = 0; n < 8; n++)
#pragma unroll
                for (int q = 0; q < 4; q++) sc[mb][n][q] = 0.f;
#pragma unroll
        for (int ks = 0; ks < 8; ks++) {
            int kb = ks * 8;
            uint32_t a0[4], a1[4];
            {
                int r0 = w32 + g, r1 = w32 + 16 + g;
                a0[0] = sm.Qs[r0][kb + tg];
                a0[1] = sm.Qs[r0 + 8][kb + tg];
                a0[2] = sm.Qs[r0][kb + tg + 4];
                a0[3] = sm.Qs[r0 + 8][kb + tg + 4];
                a1[0] = sm.Qs[r1][kb + tg];
                a1[1] = sm.Qs[r1 + 8][kb + tg];
                a1[2] = sm.Qs[r1][kb + tg + 4];
                a1[3] = sm.Qs[r1 + 8][kb + tg + 4];
            }
#pragma unroll
            for (int n = 0; n < 8; n++) {
                uint32_t b0 = sm.Ks[buf][n * 8 + g][kb + tg];
                uint32_t b1 = sm.Ks[buf][n * 8 + g][kb + tg + 4];
                mma_tf32(sc[0][n], a0, b0, b1);
                mma_tf32(sc[1][n], a1, b0, b1);
            }
        }

        // ---- per-m16-block: band bias, exp2, l partials, band writes, rel_v ----
#pragma unroll
        for (int mb = 0; mb < 2; mb++) {
            const int rbase = w32 + mb * 16;
            const int rgA = qt0 + rbase + g;
            const int rgB = rgA + 8;
            const bool band = (s0 < qt0 + rbase + 20) && (s0 + 64 > qt0 + rbase - 4);

            if (band) {
#pragma unroll
                for (int n = 0; n < 8; n++) {
#pragma unroll
                    for (int e = 0; e < 2; e++) {
                        int col = s0 + n * 8 + tg * 2 + e;
                        int d0 = col - rgA + 4;
                        if ((unsigned)d0 <= 8u) sc[mb][n][e] += sm.qe[rbase + g][d0];
                        int d1 = col - rgB + 4;
                        if ((unsigned)d1 <= 8u) sc[mb][n][2 + e] += sm.qe[rbase + g + 8][d1];
                    }
                }
            }

            // P = exp2(S) (no max shift), tf32-RNE; accumulate l partials
#pragma unroll
            for (int n = 0; n < 8; n++) {
                float p0 = __uint_as_float(f2tf(ex2(sc[mb][n][0])));
                float p1 = __uint_as_float(f2tf(ex2(sc[mb][n][1])));
                float p2 = __uint_as_float(f2tf(ex2(sc[mb][n][2])));
                float p3 = __uint_as_float(f2tf(ex2(sc[mb][n][3])));
                sc[mb][n][0] = p0; sc[mb][n][1] = p1;
                sc[mb][n][2] = p2; sc[mb][n][3] = p3;
                lp[mb][0] += p0 + p1;
                lp[mb][1] += p2 + p3;
            }
            if (band) {
#pragma unroll
                for (int n = 0; n < 8; n++) {
#pragma unroll
                    for (int e = 0; e < 2; e++) {
                        int col = s0 + n * 8 + tg * 2 + e;
                        int d0 = col - rgA + 4;
                        if ((unsigned)d0 <= 8u) sm.band[rbase + g][d0] = sc[mb][n][e];
                        int d1 = col - rgB + 4;
                        if ((unsigned)d1 <= 8u) sm.band[rbase + g + 8][d1] = sc[mb][n][2 + e];
                    }
                }
                __syncwarp();
#pragma unroll
                for (int dd = 0; dd < 9; dd++) {
                    int sgA = rgA + dd - 4;
                    if (sgA >= s0 && sgA < s0 + 64) {
                        float p = sm.band[rbase + g][dd];
#pragma unroll
                        for (int n = 0; n < 8; n++) {
                            float2 e2 = *(const float2*)&sm.ev[dd][n * 8 + tg * 2];
                            of[mb][n][0] += p * e2.x;
                            of[mb][n][1] += p * e2.y;
                        }
                    }
                    int sgB = rgB + dd - 4;
                    if (sgB >= s0 && sgB < s0 + 64) {
                        float p = sm.band[rbase + g + 8][dd];
#pragma unroll
                        for (int n = 0; n < 8; n++) {
                            float2 e2 = *(const float2*)&sm.ev[dd][n * 8 + tg * 2];
                            of[mb][n][2] += p * e2.x;
                            of[mb][n][3] += p * e2.y;
                        }
                    }
                }
            }
        }

        // ---- O += P V : zero-shuffle, C-fragment reused as A operand ----
#pragma unroll
        for (int ks = 0; ks < 8; ks++) {
            uint32_t a[2][4];
#pragma unroll
            for (int mb = 0; mb < 2; mb++) {
                a[mb][0] = __float_as_uint(sc[mb][ks][0]);   // row g,   k=tg   (key 2tg)
                a[mb][1] = __float_as_uint(sc[mb][ks][2]);   // row g+8, k=tg
                a[mb][2] = __float_as_uint(sc[mb][ks][1]);   // row g,   k=tg+4 (key 2tg+1)
                a[mb][3] = __float_as_uint(sc[mb][ks][3]);   // row g+8, k=tg+4
            }
            int kb = ks * 8;
#pragma unroll
            for (int n = 0; n < 8; n++) {
                uint32_t b0 = sm.Vs[kb + tg][n * 8 + g];       // holds key sigma(tg)
                uint32_t b1 = sm.Vs[kb + tg + 4][n * 8 + g];   // holds key sigma(tg+4)
                mma_tf32(of[0][n], a[0], b0, b1);
                mma_tf32(of[1][n], a[1], b0, b1);
            }
        }
        __syncthreads();

        if (j < 15) {
            const int s1 = s0 + 64;
#pragma unroll
            for (int i = 0; i < 8; i++) {
                int idx = tid + i * 128;
                int r = idx >> 4, c4 = (idx & 15) << 2;
                cp16(&sm.Vs[vrow(r)][c4], &V[(size_t)(s1 + r) * D_SZ + c4]);
            }
            CP_COMMIT();
        }
    }

    // ---- Epilogue: one quad-reduction for l, normalize, store ----
#pragma unroll
    for (int mb = 0; mb < 2; mb++) {
        float l0 = lp[mb][0], l1 = lp[mb][1];
        l0 += __shfl_xor_sync(0xffffffffu, l0, 1);
        l0 += __shfl_xor_sync(0xffffffffu, l0, 2);
        l1 += __shfl_xor_sync(0xffffffffu, l1, 1);
        l1 += __shfl_xor_sync(0xffffffffu, l1, 2);
        float li0 = 1.0f / l0, li1 = 1.0f / l1;
        int rgA = qt0 + w32 + mb * 16 + g;
        int rgB = rgA + 8;
        float* baseA = g_att + ((size_t)(b * T_SZ + rgA)) * C_SZ + h * D_SZ;
        float* baseB = g_att + ((size_t)(b * T_SZ + rgB)) * C_SZ + h * D_SZ;
#pragma unroll
        for (int n = 0; n < 8; n++) {
            int col = n * 8 + tg * 2;
            *(float2*)&baseA[col] =
                make_float2(of[mb][n][0] * li0, of[mb][n][1] * li0);
            *(float2*)&baseB[col] =
                make_float2(of[mb][n][2] * li1, of[mb][n][3] * li1);
        }
    }
}

// ---------------------------------------------------------------------------
// Launch
// ---------------------------------------------------------------------------
extern "C" void kernel_launch(void* const* d_in, const int* in_sizes, int n_in,
                              void* d_out, int out_size)
{
    const float* x    = (const float*)d_in[0];
    const float* c    = (const float*)d_in[1];
    const float* Wq   = (const float*)d_in[2];
    const float* bq   = (const float*)d_in[3];
    const float* Wk   = (const float*)d_in[4];
    const float* bk   = (const float*)d_in[5];
    const float* Wv   = (const float*)d_in[6];
    const float* bv   = (const float*)d_in[7];
    const float* Wo   = (const float*)d_in[8];
    const float* bo   = (const float*)d_in[9];
    const float* embk = (const float*)d_in[10];
    const float* embv = (const float*)d_in[11];
    float* out = (float*)d_out;

    (void)cudaFuncSetAttribute(attn_kernel,
                               cudaFuncAttributeMaxDynamicSharedMemorySize,
                               (int)sizeof(AttnSmem));
    (void)cudaFuncSetAttribute(gemm_tf32_kernel,
                               cudaFuncAttributeMaxDynamicSharedMemorySize,
                               (int)sizeof(GemmSmem));

    prew_kernel<<<(4 * WGRP + 255) / 256, 256>>>(Wq, Wk, Wv, Wo);
    gemm_tf32_kernel<<<dim3(32, 24), 128, sizeof(GemmSmem)>>>(
        x, c, bq, bk, bv, bo, nullptr, 0);
    attn_kernel<<<dim3(T_SZ / 128, H_SZ, B_SZ), 128, sizeof(AttnSmem)>>>(embk, embv);
    gemm_tf32_kernel<<<dim3(32, 8), 128, sizeof(GemmSmem)>>>(
        x, c, bq, bk, bv, bo, out, 3);
}

// round 12
// speedup vs baseline: 1.5382x; 1.5382x over previous
#include <cuda_runtime.h>
#include <cstdint>

#define B_SZ 4
#define T_SZ 1024
#define C_SZ 512
#define H_SZ 8
#define D_SZ 64

// Q pre-scale: 1/sqrt(64) * log2(e)  (softmax in exp2 domain)
#define Q_SCALE 0.18033688011112042f

__device__ float g_w[4][512 * 512];                // Wq*s, Wk, Wv, Wo (tf32)
__device__ float g_q[B_SZ * H_SZ * T_SZ * D_SZ];   // scaled + tf32
__device__ float g_k[B_SZ * H_SZ * T_SZ * D_SZ];   // tf32
__device__ float g_v[B_SZ * H_SZ * T_SZ * D_SZ];   // tf32
__device__ float g_att[B_SZ * T_SZ * C_SZ];

__device__ __forceinline__ uint32_t f2tf(float x) {
    uint32_t u;
    asm("cvt.rna.tf32.f32 %0, %1;" : "=r"(u) : "f"(x));
    return u;
}

__device__ __forceinline__ float ex2(float x) {
    float y;
    asm("ex2.approx.ftz.f32 %0, %1;" : "=f"(y) : "f"(x));
    return y;
}

__device__ __forceinline__ void mma_tf32(float c[4], const uint32_t a[4],
                                         uint32_t b0, uint32_t b1) {
    asm volatile(
        "mma.sync.aligned.m16n8k8.row.col.f32.tf32.tf32.f32 "
        "{%0,%1,%2,%3}, {%4,%5,%6,%7}, {%8,%9}, {%0,%1,%2,%3};\n"
        : "+f"(c[0]), "+f"(c[1]), "+f"(c[2]), "+f"(c[3])
        : "r"(a[0]), "r"(a[1]), "r"(a[2]), "r"(a[3]), "r"(b0), "r"(b1));
}

__device__ __forceinline__ void cp16(void* dst_smem, const void* src) {
    uint32_t d = (uint32_t)__cvta_generic_to_shared(dst_smem);
    asm volatile("cp.async.cg.shared.global [%0], [%1], 16;" :: "r"(d), "l"(src));
}
#define CP_COMMIT() asm volatile("cp.async.commit_group;" ::: "memory")

// ---------------------------------------------------------------------------
// Preconvert weights only: Wq*Q_SCALE, Wk, Wv, Wo -> tf32 in g_w.
// ---------------------------------------------------------------------------
#define WGRP (512 * 512 / 8)

__global__ __launch_bounds__(256) void prew_kernel(
    const float* __restrict__ Wq, const float* __restrict__ Wk,
    const float* __restrict__ Wv, const float* __restrict__ Wo)
{
    int gid = blockIdx.x * 256 + threadIdx.x;
    if (gid >= 4 * WGRP) return;
    int wi = gid / WGRP;
    int off = (gid - wi * WGRP) * 8;
    const float* src = (wi == 0) ? Wq : (wi == 1) ? Wk : (wi == 2) ? Wv : Wo;
    float s = (wi == 0) ? Q_SCALE : 1.0f;
    float4 f0 = *(const float4*)&src[off];
    float4 f1 = *(const float4*)&src[off + 4];
    *(uint4*)&g_w[wi][off] =
        make_uint4(f2tf(f0.x * s), f2tf(f0.y * s), f2tf(f0.z * s), f2tf(f0.w * s));
    *(uint4*)&g_w[wi][off + 4] =
        make_uint4(f2tf(f1.x * s), f2tf(f1.y * s), f2tf(f1.z * s), f2tf(f1.w * s));
}

// ---------------------------------------------------------------------------
// tf32 GEMM (R6 config): 128 threads, 4 warps (2x2), warp tile 64x32.
// cp.async double-buffered; weights preconverted tf32; A cvt at frag load.
// mode 0: fused QKV — grid (32, 24). mode 3: g_att @ Wo + bo — grid (32, 8).
// ---------------------------------------------------------------------------
struct GemmSmem {
    float As[2][128][36];   // raw f32 activations
    float Bs[2][32][72];    // tf32 bits (preconverted weights)
};

__global__ __launch_bounds__(128, 2) void gemm_tf32_kernel(
    const float* __restrict__ x, const float* __restrict__ cc,
    const float* __restrict__ bq, const float* __restrict__ bk,
    const float* __restrict__ bv, const float* __restrict__ bo,
    float* __restrict__ out_ext, int mode)
{
    extern __shared__ char raw[];
    GemmSmem& sm = *reinterpret_cast<GemmSmem*>(raw);

    const float* A; const float* W; const float* bias; int sel;
    int n0;
    if (mode == 0) {
        sel = blockIdx.y >> 3;
        A = (sel == 0) ? x : cc;
        W = g_w[sel];
        bias = (sel == 0) ? bq : (sel == 1) ? bk : bv;
        n0 = (blockIdx.y & 7) * 64;
    } else {
        sel = 3;
        A = g_att; W = g_w[3]; bias = bo;
        n0 = blockIdx.y * 64;
    }
    const int m0 = blockIdx.x * 128;
    const int tid = threadIdx.x;
    const int lane = tid & 31;
    const int wid = tid >> 5;
    const int g = lane >> 2;
    const int tg = lane & 3;
    const int wm = wid >> 1;
    const int wn = wid & 1;

    auto issue_tile = [&](int kt, int bufi) {
        int kb = kt * 32;
#pragma unroll
        for (int i = 0; i < 8; i++) {
            int idx = tid + i * 128;
            int r = idx >> 3;
            int kk = (idx & 7) << 2;
            cp16(&sm.As[bufi][r][kk], &A[(size_t)(m0 + r) * 512 + kb + kk]);
        }
#pragma unroll
        for (int i = 0; i < 4; i++) {
            int idx = tid + i * 128;
            int kk = idx >> 4;
            int nn = (idx & 15) << 2;
            cp16(&sm.Bs[bufi][kk][nn], &W[(size_t)(kb + kk) * 512 + n0 + nn]);
        }
        CP_COMMIT();
    };

    float c[4][4][4];
#pragma unroll
    for (int i = 0; i < 4; i++)
#pragma unroll
        for (int j = 0; j < 4; j++)
#pragma unroll
            for (int q = 0; q < 4; q++) c[i][j][q] = 0.f;

    issue_tile(0, 0);

    for (int kt = 0; kt < 16; kt++) {
        asm volatile("cp.async.wait_group 0;" ::: "memory");
        __syncthreads();
        if (kt < 15) issue_tile(kt + 1, (kt + 1) & 1);
        const float (*Af)[36] = sm.As[kt & 1];
        const float (*Bf)[72] = sm.Bs[kt & 1];

#pragma unroll
        for (int ks = 0; ks < 4; ks++) {
            int kb = ks * 8;
            uint32_t a[4][4], b[4][2];
#pragma unroll
            for (int i = 0; i < 4; i++) {
                int mr = wm * 64 + i * 16 + g;
                a[i][0] = f2tf(Af[mr][kb + tg]);
                a[i][1] = f2tf(Af[mr + 8][kb + tg]);
                a[i][2] = f2tf(Af[mr][kb + tg + 4]);
                a[i][3] = f2tf(Af[mr + 8][kb + tg + 4]);
            }
#pragma unroll
            for (int j = 0; j < 4; j++) {
                int nc = wn * 32 + j * 8 + g;
                b[j][0] = __float_as_uint(Bf[kb + tg][nc]);
                b[j][1] = __float_as_uint(Bf[kb + tg + 4][nc]);
            }
#pragma unroll
            for (int i = 0; i < 4; i++)
#pragma unroll
                for (int j = 0; j < 4; j++) mma_tf32(c[i][j], a[i], b[j][0], b[j][1]);
        }
    }

#pragma unroll
    for (int i = 0; i < 4; i++) {
        int r0 = m0 + wm * 64 + i * 16 + g;
#pragma unroll
        for (int j = 0; j < 4; j++) {
            int col0 = n0 + wn * 32 + j * 8 + tg * 2;
            float bv0 = bias[col0], bv1 = bias[col0 + 1];
            if (sel == 0) { bv0 *= Q_SCALE; bv1 *= Q_SCALE; }
            float v00 = c[i][j][0] + bv0;
            float v01 = c[i][j][1] + bv1;
            float v10 = c[i][j][2] + bv0;
            float v11 = c[i][j][3] + bv1;
            if (sel < 3) {
                v00 = __uint_as_float(f2tf(v00));
                v01 = __uint_as_float(f2tf(v01));
                v10 = __uint_as_float(f2tf(v10));
                v11 = __uint_as_float(f2tf(v11));
                float* outb = (sel == 0) ? g_q : (sel == 1) ? g_k : g_v;
                int hh = col0 >> 6;
                int d = col0 & 63;
                {
                    int bb = r0 >> 10, t = r0 & 1023;
                    size_t base = ((((size_t)bb * H_SZ + hh) << 10) + t) * D_SZ + d;
                    *(float2*)&outb[base] = make_float2(v00, v01);
                }
                {
                    int r1 = r0 + 8;
                    int bb = r1 >> 10, t = r1 & 1023;
                    size_t base = ((((size_t)bb * H_SZ + hh) << 10) + t) * D_SZ + d;
                    *(float2*)&outb[base] = make_float2(v10, v11);
                }
            } else {
                *(float2*)&out_ext[(size_t)r0 * 512 + col0] = make_float2(v00, v01);
                *(float2*)&out_ext[(size_t)(r0 + 8) * 512 + col0] = make_float2(v10, v11);
            }
        }
    }
}

// ---------------------------------------------------------------------------
// Flash attention v10: shuffle-free PV (sigma-permuted V rows) + Q fragments
// for ks 0-3 hoisted to registers (halves Q LDS in the hot loop).
// No online rescale (scores bounded). 128-q CTA, 4 warps, warp tile m32.
// ---------------------------------------------------------------------------
struct AttnSmem {
    uint32_t Qs[128][68];
    uint32_t Ks[2][64][68];
    uint32_t Vs[64][72];      // rows sigma-permuted within 8-groups
    float ek[9][64];
    float ev[9][64];
    float qe[128][12];
    float band[128][12];
};

__global__ __launch_bounds__(128, 2) void attn_kernel(const float* __restrict__ embk,
                                                      const float* __restrict__ embv)
{
    extern __shared__ char smem_raw[];
    AttnSmem& sm = *reinterpret_cast<AttnSmem*>(smem_raw);

    const int tid = threadIdx.x;
    const int lane = tid & 31;
    const int wid = tid >> 5;
    const int g = lane >> 2;
    const int tg = lane & 3;
    const int w32 = wid * 32;
    const int qt0 = blockIdx.x * 128;
    const int h = blockIdx.y;
    const int b = blockIdx.z;
    const size_t head_off = ((size_t)(b * H_SZ + h)) * T_SZ * D_SZ;
    const float* Q = g_q + head_off;
    const float* K = g_k + head_off;
    const float* V = g_v + head_off;

    for (int i = tid; i < 128 * 16; i += 128) {
        int r = i >> 4, c4 = (i & 15) << 2;
        *(uint4*)&sm.Qs[r][c4] = *(const uint4*)&Q[(size_t)(qt0 + r) * D_SZ + c4];
    }
    for (int i = tid; i < 9 * 64; i += 128) {
        sm.ek[0][i] = embk[i];
        sm.ev[0][i] = embv[i];
    }
    __syncthreads();

    for (int i = tid; i < 128 * 9; i += 128) {
        int t = i / 9, dd = i - t * 9;
        const float* qrow = (const float*)sm.Qs[t];
        float s = 0.f;
#pragma unroll
        for (int d = 0; d < 64; d += 4) {
            float4 q4 = *(const float4*)&qrow[d];
            float4 e4 = *(const float4*)&sm.ek[dd][d];
            s += q4.x * e4.x + q4.y * e4.y + q4.z * e4.z + q4.w * e4.w;
        }
        sm.qe[t][dd] = s;
    }

    // V row permutation: dest row for source key r (sigma^-1 within 8-group)
    auto vrow = [](int r) {
        return (r & 56) | ((r & 1) << 2) | ((r >> 1) & 3);
    };

#pragma unroll
    for (int i = 0; i < 8; i++) {
        int idx = tid + i * 128;
        int r = idx >> 4, c4 = (idx & 15) << 2;
        cp16(&sm.Ks[0][r][c4], &K[(size_t)r * D_SZ + c4]);
        cp16(&sm.Vs[vrow(r)][c4], &V[(size_t)r * D_SZ + c4]);
    }
    CP_COMMIT();
    __syncthreads();   // qe/Qs writes visible to all before hot loop

    // Hoist Q A-fragments for ks = 0..3 into registers (ks 4..7 stay in smem)
    uint32_t qh[4][8];
#pragma unroll
    for (int ks = 0; ks < 4; ks++) {
        int kb = ks * 8;
        int r0 = w32 + g, r1 = w32 + 16 + g;
        qh[ks][0] = sm.Qs[r0][kb + tg];
        qh[ks][1] = sm.Qs[r0 + 8][kb + tg];
        qh[ks][2] = sm.Qs[r0][kb + tg + 4];
        qh[ks][3] = sm.Qs[r0 + 8][kb + tg + 4];
        qh[ks][4] = sm.Qs[r1][kb + tg];
        qh[ks][5] = sm.Qs[r1 + 8][kb + tg];
        qh[ks][6] = sm.Qs[r1][kb + tg + 4];
        qh[ks][7] = sm.Qs[r1 + 8][kb + tg + 4];
    }

    float of[2][8][4];
#pragma unroll
    for (int mb = 0; mb < 2; mb++)
#pragma unroll
        for (int n = 0; n < 8; n++)
#pragma unroll
            for (int q = 0; q < 4; q++) of[mb][n][q] = 0.f;
    float lp[2][2] = {{0.f, 0.f}, {0.f, 0.f}};   // per-thread partial l sums

    for (int j = 0; j < 16; j++) {
        const int s0 = j * 64;
        if (j < 15) {
            const int s1 = s0 + 64;
#pragma unroll
            for (int i = 0; i < 8; i++) {
                int idx = tid + i * 128;
                int r = idx >> 4, c4 = (idx & 15) << 2;
                cp16(&sm.Ks[(j + 1) & 1][r][c4], &K[(size_t)(s1 + r) * D_SZ + c4]);
            }
            CP_COMMIT();
            asm volatile("cp.async.wait_group 1;" ::: "memory");
        } else {
            asm volatile("cp.async.wait_group 0;" ::: "memory");
        }
        __syncthreads();
        const int buf = j & 1;

        // ---- S = Q K^T ----
        float sc[2][8][4];
#pragma unroll
        for (int mb = 0; mb < 2; mb++)
#pragma unroll
            for (int n = 0; n < 8; n++)
#pragma unroll
                for (int q = 0; q < 4; q++) sc[mb][n][q] = 0.f;
#pragma unroll
        for (int ks = 0; ks < 8; ks++) {
            int kb = ks * 8;
            uint32_t a0[4], a1[4];
            if (ks < 4) {
                a0[0] = qh[ks][0]; a0[1] = qh[ks][1];
                a0[2] = qh[ks][2]; a0[3] = qh[ks][3];
                a1[0] = qh[ks][4]; a1[1] = qh[ks][5];
                a1[2] = qh[ks][6]; a1[3] = qh[ks][7];
            } else {
                int r0 = w32 + g, r1 = w32 + 16 + g;
                a0[0] = sm.Qs[r0][kb + tg];
                a0[1] = sm.Qs[r0 + 8][kb + tg];
                a0[2] = sm.Qs[r0][kb + tg + 4];
                a0[3] = sm.Qs[r0 + 8][kb + tg + 4];
                a1[0] = sm.Qs[r1][kb + tg];
                a1[1] = sm.Qs[r1 + 8][kb + tg];
                a1[2] = sm.Qs[r1][kb + tg + 4];
                a1[3] = sm.Qs[r1 + 8][kb + tg + 4];
            }
#pragma unroll
            for (int n = 0; n < 8; n++) {
                uint32_t b0 = sm.Ks[buf][n * 8 + g][kb + tg];
                uint32_t b1 = sm.Ks[buf][n * 8 + g][kb + tg + 4];
                mma_tf32(sc[0][n], a0, b0, b1);
                mma_tf32(sc[1][n], a1, b0, b1);
            }
        }

        // ---- per-m16-block: band bias, exp2, l partials, band writes, rel_v ----
#pragma unroll
        for (int mb = 0; mb < 2; mb++) {
            const int rbase = w32 + mb * 16;
            const int rgA = qt0 + rbase + g;
            const int rgB = rgA + 8;
            const bool band = (s0 < qt0 + rbase + 20) && (s0 + 64 > qt0 + rbase - 4);

            if (band) {
#pragma unroll
                for (int n = 0; n < 8; n++) {
#pragma unroll
                    for (int e = 0; e < 2; e++) {
                        int col = s0 + n * 8 + tg * 2 + e;
                        int d0 = col - rgA + 4;
                        if ((unsigned)d0 <= 8u) sc[mb][n][e] += sm.qe[rbase + g][d0];
                        int d1 = col - rgB + 4;
                        if ((unsigned)d1 <= 8u) sc[mb][n][2 + e] += sm.qe[rbase + g + 8][d1];
                    }
                }
            }

            // P = exp2(S) (no max shift), tf32-RNE; accumulate l partials
#pragma unroll
            for (int n = 0; n < 8; n++) {
                float p0 = __uint_as_float(f2tf(ex2(sc[mb][n][0])));
                float p1 = __uint_as_float(f2tf(ex2(sc[mb][n][1])));
                float p2 = __uint_as_float(f2tf(ex2(sc[mb][n][2])));
                float p3 = __uint_as_float(f2tf(ex2(sc[mb][n][3])));
                sc[mb][n][0] = p0; sc[mb][n][1] = p1;
                sc[mb][n][2] = p2; sc[mb][n][3] = p3;
                lp[mb][0] += p0 + p1;
                lp[mb][1] += p2 + p3;
            }
            if (band) {
#pragma unroll
                for (int n = 0; n < 8; n++) {
#pragma unroll
                    for (int e = 0; e < 2; e++) {
                        int col = s0 + n * 8 + tg * 2 + e;
                        int d0 = col - rgA + 4;
                        if ((unsigned)d0 <= 8u) sm.band[rbase + g][d0] = sc[mb][n][e];
                        int d1 = col - rgB + 4;
                        if ((unsigned)d1 <= 8u) sm.band[rbase + g + 8][d1] = sc[mb][n][2 + e];
                    }
                }
                __syncwarp();
#pragma unroll
                for (int dd = 0; dd < 9; dd++) {
                    int sgA = rgA + dd - 4;
                    if (sgA >= s0 && sgA < s0 + 64) {
                        float p = sm.band[rbase + g][dd];
#pragma unroll
                        for (int n = 0; n < 8; n++) {
                            float2 e2 = *(const float2*)&sm.ev[dd][n * 8 + tg * 2];
                            of[mb][n][0] += p * e2.x;
                            of[mb][n][1] += p * e2.y;
                        }
                    }
                    int sgB = rgB + dd - 4;
                    if (sgB >= s0 && sgB < s0 + 64) {
                        float p = sm.band[rbase + g + 8][dd];
#pragma unroll
                        for (int n = 0; n < 8; n++) {
                            float2 e2 = *(const float2*)&sm.ev[dd][n * 8 + tg * 2];
                            of[mb][n][2] += p * e2.x;
                            of[mb][n][3] += p * e2.y;
                        }
                    }
                }
            }
        }

        // ---- O += P V : zero-shuffle, C-fragment reused as A operand ----
#pragma unroll
        for (int ks = 0; ks < 8; ks++) {
            uint32_t a[2][4];
#pragma unroll
            for (int mb = 0; mb < 2; mb++) {
                a[mb][0] = __float_as_uint(sc[mb][ks][0]);   // row g,   k=tg   (key 2tg)
                a[mb][1] = __float_as_uint(sc[mb][ks][2]);   // row g+8, k=tg
                a[mb][2] = __float_as_uint(sc[mb][ks][1]);   // row g,   k=tg+4 (key 2tg+1)
                a[mb][3] = __float_as_uint(sc[mb][ks][3]);   // row g+8, k=tg+4
            }
            int kb = ks * 8;
#pragma unroll
            for (int n = 0; n < 8; n++) {
                uint32_t b0 = sm.Vs[kb + tg][n * 8 + g];       // holds key sigma(tg)
                uint32_t b1 = sm.Vs[kb + tg + 4][n * 8 + g];   // holds key sigma(tg+4)
                mma_tf32(of[0][n], a[0], b0, b1);
                mma_tf32(of[1][n], a[1], b0, b1);
            }
        }
        __syncthreads();

        if (j < 15) {
            const int s1 = s0 + 64;
#pragma unroll
            for (int i = 0; i < 8; i++) {
                int idx = tid + i * 128;
                int r = idx >> 4, c4 = (idx & 15) << 2;
                cp16(&sm.Vs[vrow(r)][c4], &V[(size_t)(s1 + r) * D_SZ + c4]);
            }
            CP_COMMIT();
        }
    }

    // ---- Epilogue: one quad-reduction for l, normalize, store ----
#pragma unroll
    for (int mb = 0; mb < 2; mb++) {
        float l0 = lp[mb][0], l1 = lp[mb][1];
        l0 += __shfl_xor_sync(0xffffffffu, l0, 1);
        l0 += __shfl_xor_sync(0xffffffffu, l0, 2);
        l1 += __shfl_xor_sync(0xffffffffu, l1, 1);
        l1 += __shfl_xor_sync(0xffffffffu, l1, 2);
        float li0 = 1.0f / l0, li1 = 1.0f / l1;
        int rgA = qt0 + w32 + mb * 16 + g;
        int rgB = rgA + 8;
        float* baseA = g_att + ((size_t)(b * T_SZ + rgA)) * C_SZ + h * D_SZ;
        float* baseB = g_att + ((size_t)(b * T_SZ + rgB)) * C_SZ + h * D_SZ;
#pragma unroll
        for (int n = 0; n < 8; n++) {
            int col = n * 8 + tg * 2;
            *(float2*)&baseA[col] =
                make_float2(of[mb][n][0] * li0, of[mb][n][1] * li0);
            *(float2*)&baseB[col] =
                make_float2(of[mb][n][2] * li1, of[mb][n][3] * li1);
        }
    }
}

// ---------------------------------------------------------------------------
// Launch
// ---------------------------------------------------------------------------
extern "C" void kernel_launch(void* const* d_in, const int* in_sizes, int n_in,
                              void* d_out, int out_size)
{
    const float* x    = (const float*)d_in[0];
    const float* c    = (const float*)d_in[1];
    const float* Wq   = (const float*)d_in[2];
    const float* bq   = (const float*)d_in[3];
    const float* Wk   = (const float*)d_in[4];
    const float* bk   = (const float*)d_in[5];
    const float* Wv   = (const float*)d_in[6];
    const float* bv   = (const float*)d_in[7];
    const float* Wo   = (const float*)d_in[8];
    const float* bo   = (const float*)d_in[9];
    const float* embk = (const float*)d_in[10];
    const float* embv = (const float*)d_in[11];
    float* out = (float*)d_out;

    (void)cudaFuncSetAttribute(attn_kernel,
                               cudaFuncAttributeMaxDynamicSharedMemorySize,
                               (int)sizeof(AttnSmem));
    (void)cudaFuncSetAttribute(gemm_tf32_kernel,
                               cudaFuncAttributeMaxDynamicSharedMemorySize,
                               (int)sizeof(GemmSmem));

    prew_kernel<<<(4 * WGRP + 255) / 256, 256>>>(Wq, Wk, Wv, Wo);
    gemm_tf32_kernel<<<dim3(32, 24), 128, sizeof(GemmSmem)>>>(
        x, c, bq, bk, bv, bo, nullptr, 0);
    attn_kernel<<<dim3(T_SZ / 128, H_SZ, B_SZ), 128, sizeof(AttnSmem)>>>(embk, embv);
    gemm_tf32_kernel<<<dim3(32, 8), 128, sizeof(GemmSmem)>>>(
        x, c, bq, bk, bv, bo, out, 3);
}

// round 13
// speedup vs baseline: 1.6142x; 1.0494x over previous
#include <cuda_runtime.h>
#include <cstdint>

#define B_SZ 4
#define T_SZ 1024
#define C_SZ 512
#define H_SZ 8
#define D_SZ 64

// Q pre-scale: 1/sqrt(64) * log2(e)  (softmax in exp2 domain)
#define Q_SCALE 0.18033688011112042f

__device__ float g_w[4][512 * 512];                // Wq*s, Wk, Wv, Wo (tf32)
__device__ float g_q[B_SZ * H_SZ * T_SZ * D_SZ];   // scaled + tf32
__device__ float g_k[B_SZ * H_SZ * T_SZ * D_SZ];   // tf32
__device__ float g_v[B_SZ * H_SZ * T_SZ * D_SZ];   // tf32
__device__ float g_att[B_SZ * T_SZ * C_SZ];

__device__ __forceinline__ uint32_t f2tf(float x) {
    uint32_t u;
    asm("cvt.rna.tf32.f32 %0, %1;" : "=r"(u) : "f"(x));
    return u;
}

__device__ __forceinline__ float ex2(float x) {
    float y;
    asm("ex2.approx.ftz.f32 %0, %1;" : "=f"(y) : "f"(x));
    return y;
}

__device__ __forceinline__ void mma_tf32(float c[4], const uint32_t a[4],
                                         uint32_t b0, uint32_t b1) {
    asm volatile(
        "mma.sync.aligned.m16n8k8.row.col.f32.tf32.tf32.f32 "
        "{%0,%1,%2,%3}, {%4,%5,%6,%7}, {%8,%9}, {%0,%1,%2,%3};\n"
        : "+f"(c[0]), "+f"(c[1]), "+f"(c[2]), "+f"(c[3])
        : "r"(a[0]), "r"(a[1]), "r"(a[2]), "r"(a[3]), "r"(b0), "r"(b1));
}

__device__ __forceinline__ void cp16(void* dst_smem, const void* src) {
    uint32_t d = (uint32_t)__cvta_generic_to_shared(dst_smem);
    asm volatile("cp.async.cg.shared.global [%0], [%1], 16;" :: "r"(d), "l"(src));
}
#define CP_COMMIT() asm volatile("cp.async.commit_group;" ::: "memory")

// ---------------------------------------------------------------------------
// Preconvert weights only: Wq*Q_SCALE, Wk, Wv, Wo -> tf32 in g_w.
// ---------------------------------------------------------------------------
#define WGRP (512 * 512 / 8)

__global__ __launch_bounds__(256) void prew_kernel(
    const float* __restrict__ Wq, const float* __restrict__ Wk,
    const float* __restrict__ Wv, const float* __restrict__ Wo)
{
    int gid = blockIdx.x * 256 + threadIdx.x;
    if (gid >= 4 * WGRP) return;
    int wi = gid / WGRP;
    int off = (gid - wi * WGRP) * 8;
    const float* src = (wi == 0) ? Wq : (wi == 1) ? Wk : (wi == 2) ? Wv : Wo;
    float s = (wi == 0) ? Q_SCALE : 1.0f;
    float4 f0 = *(const float4*)&src[off];
    float4 f1 = *(const float4*)&src[off + 4];
    *(uint4*)&g_w[wi][off] =
        make_uint4(f2tf(f0.x * s), f2tf(f0.y * s), f2tf(f0.z * s), f2tf(f0.w * s));
    *(uint4*)&g_w[wi][off + 4] =
        make_uint4(f2tf(f1.x * s), f2tf(f1.y * s), f2tf(f1.z * s), f2tf(f1.w * s));
}

// ---------------------------------------------------------------------------
// QKV GEMM (big tile): CTA 128x128, 128 threads, 4 warps (2x2), warp 64x64.
// grid (32, 12): sel = by>>2 (q/k/v), n0 = (by&3)*128.
// Per warp-kstep: 16 A-LDS + 16 cvt + 16 B-LDS feed 32 MMAs (2.5 slots/MMA).
// ---------------------------------------------------------------------------
struct GemmBigSmem {
    float As[2][128][36];    // raw f32 activations
    float Bs[2][32][136];    // tf32 bits (preconverted weights)
};

__global__ __launch_bounds__(128, 2) void gemm_qkv_kernel(
    const float* __restrict__ x, const float* __restrict__ cc,
    const float* __restrict__ bq, const float* __restrict__ bk,
    const float* __restrict__ bv)
{
    extern __shared__ char raw[];
    GemmBigSmem& sm = *reinterpret_cast<GemmBigSmem*>(raw);

    const int sel = blockIdx.y >> 2;
    const float* A = (sel == 0) ? x : cc;
    const float* W = g_w[sel];
    const float* bias = (sel == 0) ? bq : (sel == 1) ? bk : bv;
    const int n0 = (blockIdx.y & 3) * 128;
    const int m0 = blockIdx.x * 128;
    const int tid = threadIdx.x;
    const int lane = tid & 31;
    const int wid = tid >> 5;
    const int g = lane >> 2;
    const int tg = lane & 3;
    const int wm = wid >> 1;
    const int wn = wid & 1;

    auto issue_tile = [&](int kt, int bufi) {
        int kb = kt * 32;
#pragma unroll
        for (int i = 0; i < 8; i++) {
            int idx = tid + i * 128;            // 0..1023
            int r = idx >> 3;
            int kk = (idx & 7) << 2;
            cp16(&sm.As[bufi][r][kk], &A[(size_t)(m0 + r) * 512 + kb + kk]);
        }
#pragma unroll
        for (int i = 0; i < 8; i++) {
            int idx = tid + i * 128;            // 0..1023
            int kk = idx >> 5;                  // 0..31
            int nn = (idx & 31) << 2;           // 0..124
            cp16(&sm.Bs[bufi][kk][nn], &W[(size_t)(kb + kk) * 512 + n0 + nn]);
        }
        CP_COMMIT();
    };

    float c[4][8][4];
#pragma unroll
    for (int i = 0; i < 4; i++)
#pragma unroll
        for (int j = 0; j < 8; j++)
#pragma unroll
            for (int q = 0; q < 4; q++) c[i][j][q] = 0.f;

    issue_tile(0, 0);

    for (int kt = 0; kt < 16; kt++) {
        asm volatile("cp.async.wait_group 0;" ::: "memory");
        __syncthreads();
        if (kt < 15) issue_tile(kt + 1, (kt + 1) & 1);
        const float (*Af)[36] = sm.As[kt & 1];
        const float (*Bf)[136] = sm.Bs[kt & 1];

#pragma unroll
        for (int ks = 0; ks < 4; ks++) {
            int kb = ks * 8;
            uint32_t a[4][4], b[8][2];
#pragma unroll
            for (int i = 0; i < 4; i++) {
                int mr = wm * 64 + i * 16 + g;
                a[i][0] = f2tf(Af[mr][kb + tg]);
                a[i][1] = f2tf(Af[mr + 8][kb + tg]);
                a[i][2] = f2tf(Af[mr][kb + tg + 4]);
                a[i][3] = f2tf(Af[mr + 8][kb + tg + 4]);
            }
#pragma unroll
            for (int j = 0; j < 8; j++) {
                int nc = wn * 64 + j * 8 + g;
                b[j][0] = __float_as_uint(Bf[kb + tg][nc]);
                b[j][1] = __float_as_uint(Bf[kb + tg + 4][nc]);
            }
#pragma unroll
            for (int i = 0; i < 4; i++)
#pragma unroll
                for (int j = 0; j < 8; j++) mma_tf32(c[i][j], a[i], b[j][0], b[j][1]);
        }
    }

#pragma unroll
    for (int i = 0; i < 4; i++) {
        int r0 = m0 + wm * 64 + i * 16 + g;
#pragma unroll
        for (int j = 0; j < 8; j++) {
            int col0 = n0 + wn * 64 + j * 8 + tg * 2;
            float bv0 = bias[col0], bv1 = bias[col0 + 1];
            if (sel == 0) { bv0 *= Q_SCALE; bv1 *= Q_SCALE; }
            float v00 = __uint_as_float(f2tf(c[i][j][0] + bv0));
            float v01 = __uint_as_float(f2tf(c[i][j][1] + bv1));
            float v10 = __uint_as_float(f2tf(c[i][j][2] + bv0));
            float v11 = __uint_as_float(f2tf(c[i][j][3] + bv1));
            float* outb = (sel == 0) ? g_q : (sel == 1) ? g_k : g_v;
            int hh = col0 >> 6;
            int d = col0 & 63;
            {
                int bb = r0 >> 10, t = r0 & 1023;
                size_t base = ((((size_t)bb * H_SZ + hh) << 10) + t) * D_SZ + d;
                *(float2*)&outb[base] = make_float2(v00, v01);
            }
            {
                int r1 = r0 + 8;
                int bb = r1 >> 10, t = r1 & 1023;
                size_t base = ((((size_t)bb * H_SZ + hh) << 10) + t) * D_SZ + d;
                *(float2*)&outb[base] = make_float2(v10, v11);
            }
        }
    }
}

// ---------------------------------------------------------------------------
// Output GEMM (R6 config, mode-3 only): 128 threads, warp tile 64x32.
// ---------------------------------------------------------------------------
struct GemmSmem {
    float As[2][128][36];   // g_att (f32 values, already tf32-rounded)
    float Bs[2][32][72];    // tf32 bits (preconverted Wo)
};

__global__ __launch_bounds__(128, 2) void gemm_out_kernel(
    const float* __restrict__ bo, float* __restrict__ out_ext)
{
    extern __shared__ char raw[];
    GemmSmem& sm = *reinterpret_cast<GemmSmem*>(raw);

    const float* A = g_att;
    const float* W = g_w[3];
    const int n0 = blockIdx.y * 64;
    const int m0 = blockIdx.x * 128;
    const int tid = threadIdx.x;
    const int lane = tid & 31;
    const int wid = tid >> 5;
    const int g = lane >> 2;
    const int tg = lane & 3;
    const int wm = wid >> 1;
    const int wn = wid & 1;

    auto issue_tile = [&](int kt, int bufi) {
        int kb = kt * 32;
#pragma unroll
        for (int i = 0; i < 8; i++) {
            int idx = tid + i * 128;
            int r = idx >> 3;
            int kk = (idx & 7) << 2;
            cp16(&sm.As[bufi][r][kk], &A[(size_t)(m0 + r) * 512 + kb + kk]);
        }
#pragma unroll
        for (int i = 0; i < 4; i++) {
            int idx = tid + i * 128;
            int kk = idx >> 4;
            int nn = (idx & 15) << 2;
            cp16(&sm.Bs[bufi][kk][nn], &W[(size_t)(kb + kk) * 512 + n0 + nn]);
        }
        CP_COMMIT();
    };

    float c[4][4][4];
#pragma unroll
    for (int i = 0; i < 4; i++)
#pragma unroll
        for (int j = 0; j < 4; j++)
#pragma unroll
            for (int q = 0; q < 4; q++) c[i][j][q] = 0.f;

    issue_tile(0, 0);

    for (int kt = 0; kt < 16; kt++) {
        asm volatile("cp.async.wait_group 0;" ::: "memory");
        __syncthreads();
        if (kt < 15) issue_tile(kt + 1, (kt + 1) & 1);
        const float (*Af)[36] = sm.As[kt & 1];
        const float (*Bf)[72] = sm.Bs[kt & 1];

#pragma unroll
        for (int ks = 0; ks < 4; ks++) {
            int kb = ks * 8;
            uint32_t a[4][4], b[4][2];
#pragma unroll
            for (int i = 0; i < 4; i++) {
                int mr = wm * 64 + i * 16 + g;
                a[i][0] = f2tf(Af[mr][kb + tg]);
                a[i][1] = f2tf(Af[mr + 8][kb + tg]);
                a[i][2] = f2tf(Af[mr][kb + tg + 4]);
                a[i][3] = f2tf(Af[mr + 8][kb + tg + 4]);
            }
#pragma unroll
            for (int j = 0; j < 4; j++) {
                int nc = wn * 32 + j * 8 + g;
                b[j][0] = __float_as_uint(Bf[kb + tg][nc]);
                b[j][1] = __float_as_uint(Bf[kb + tg + 4][nc]);
            }
#pragma unroll
            for (int i = 0; i < 4; i++)
#pragma unroll
                for (int j = 0; j < 4; j++) mma_tf32(c[i][j], a[i], b[j][0], b[j][1]);
        }
    }

#pragma unroll
    for (int i = 0; i < 4; i++) {
        int r0 = m0 + wm * 64 + i * 16 + g;
#pragma unroll
        for (int j = 0; j < 4; j++) {
            int col0 = n0 + wn * 32 + j * 8 + tg * 2;
            float v00 = c[i][j][0] + bo[col0];
            float v01 = c[i][j][1] + bo[col0 + 1];
            float v10 = c[i][j][2] + bo[col0];
            float v11 = c[i][j][3] + bo[col0 + 1];
            *(float2*)&out_ext[(size_t)r0 * 512 + col0] = make_float2(v00, v01);
            *(float2*)&out_ext[(size_t)(r0 + 8) * 512 + col0] = make_float2(v10, v11);
        }
    }
}

// ---------------------------------------------------------------------------
// Flash attention v10 (unchanged from R12): shuffle-free PV (sigma-permuted V
// rows) + Q fragments ks0-3 hoisted. No online rescale. 128-q CTA, m32 warps.
// ---------------------------------------------------------------------------
struct AttnSmem {
    uint32_t Qs[128][68];
    uint32_t Ks[2][64][68];
    uint32_t Vs[64][72];      // rows sigma-permuted within 8-groups
    float ek[9][64];
    float ev[9][64];
    float qe[128][12];
    float band[128][12];
};

__global__ __launch_bounds__(128, 2) void attn_kernel(const float* __restrict__ embk,
                                                      const float* __restrict__ embv)
{
    extern __shared__ char smem_raw[];
    AttnSmem& sm = *reinterpret_cast<AttnSmem*>(smem_raw);

    const int tid = threadIdx.x;
    const int lane = tid & 31;
    const int wid = tid >> 5;
    const int g = lane >> 2;
    const int tg = lane & 3;
    const int w32 = wid * 32;
    const int qt0 = blockIdx.x * 128;
    const int h = blockIdx.y;
    const int b = blockIdx.z;
    const size_t head_off = ((size_t)(b * H_SZ + h)) * T_SZ * D_SZ;
    const float* Q = g_q + head_off;
    const float* K = g_k + head_off;
    const float* V = g_v + head_off;

    for (int i = tid; i < 128 * 16; i += 128) {
        int r = i >> 4, c4 = (i & 15) << 2;
        *(uint4*)&sm.Qs[r][c4] = *(const uint4*)&Q[(size_t)(qt0 + r) * D_SZ + c4];
    }
    for (int i = tid; i < 9 * 64; i += 128) {
        sm.ek[0][i] = embk[i];
        sm.ev[0][i] = embv[i];
    }
    __syncthreads();

    for (int i = tid; i < 128 * 9; i += 128) {
        int t = i / 9, dd = i - t * 9;
        const float* qrow = (const float*)sm.Qs[t];
        float s = 0.f;
#pragma unroll
        for (int d = 0; d < 64; d += 4) {
            float4 q4 = *(const float4*)&qrow[d];
            float4 e4 = *(const float4*)&sm.ek[dd][d];
            s += q4.x * e4.x + q4.y * e4.y + q4.z * e4.z + q4.w * e4.w;
        }
        sm.qe[t][dd] = s;
    }

    auto vrow = [](int r) {
        return (r & 56) | ((r & 1) << 2) | ((r >> 1) & 3);
    };

#pragma unroll
    for (int i = 0; i < 8; i++) {
        int idx = tid + i * 128;
        int r = idx >> 4, c4 = (idx & 15) << 2;
        cp16(&sm.Ks[0][r][c4], &K[(size_t)r * D_SZ + c4]);
        cp16(&sm.Vs[vrow(r)][c4], &V[(size_t)r * D_SZ + c4]);
    }
    CP_COMMIT();
    __syncthreads();

    uint32_t qh[4][8];
#pragma unroll
    for (int ks = 0; ks < 4; ks++) {
        int kb = ks * 8;
        int r0 = w32 + g, r1 = w32 + 16 + g;
        qh[ks][0] = sm.Qs[r0][kb + tg];
        qh[ks][1] = sm.Qs[r0 + 8][kb + tg];
        qh[ks][2] = sm.Qs[r0][kb + tg + 4];
        qh[ks][3] = sm.Qs[r0 + 8][kb + tg + 4];
        qh[ks][4] = sm.Qs[r1][kb + tg];
        qh[ks][5] = sm.Qs[r1 + 8][kb + tg];
        qh[ks][6] = sm.Qs[r1][kb + tg + 4];
        qh[ks][7] = sm.Qs[r1 + 8][kb + tg + 4];
    }

    float of[2][8][4];
#pragma unroll
    for (int mb = 0; mb < 2; mb++)
#pragma unroll
        for (int n = 0; n < 8; n++)
#pragma unroll
            for (int q = 0; q < 4; q++) of[mb][n][q] = 0.f;
    float lp[2][2] = {{0.f, 0.f}, {0.f, 0.f}};

    for (int j = 0; j < 16; j++) {
        const int s0 = j * 64;
        if (j < 15) {
            const int s1 = s0 + 64;
#pragma unroll
            for (int i = 0; i < 8; i++) {
                int idx = tid + i * 128;
                int r = idx >> 4, c4 = (idx & 15) << 2;
                cp16(&sm.Ks[(j + 1) & 1][r][c4], &K[(size_t)(s1 + r) * D_SZ + c4]);
            }
            CP_COMMIT();
            asm volatile("cp.async.wait_group 1;" ::: "memory");
        } else {
            asm volatile("cp.async.wait_group 0;" ::: "memory");
        }
        __syncthreads();
        const int buf = j & 1;

        float sc[2][8][4];
#pragma unroll
        for (int mb = 0; mb < 2; mb++)
#pragma unroll
            for (int n = 0; n < 8; n++)
#pragma unroll
                for (int q = 0; q < 4; q++) sc[mb][n][q] = 0.f;
#pragma unroll
        for (int ks = 0; ks < 8; ks++) {
            int kb = ks * 8;
            uint32_t a0[4], a1[4];
            if (ks < 4) {
                a0[0] = qh[ks][0]; a0[1] = qh[ks][1];
                a0[2] = qh[ks][2]; a0[3] = qh[ks][3];
                a1[0] = qh[ks][4]; a1[1] = qh[ks][5];
                a1[2] = qh[ks][6]; a1[3] = qh[ks][7];
            } else {
                int r0 = w32 + g, r1 = w32 + 16 + g;
                a0[0] = sm.Qs[r0][kb + tg];
                a0[1] = sm.Qs[r0 + 8][kb + tg];
                a0[2] = sm.Qs[r0][kb + tg + 4];
                a0[3] = sm.Qs[r0 + 8][kb + tg + 4];
                a1[0] = sm.Qs[r1][kb + tg];
                a1[1] = sm.Qs[r1 + 8][kb + tg];
                a1[2] = sm.Qs[r1][kb + tg + 4];
                a1[3] = sm.Qs[r1 + 8][kb + tg + 4];
            }
#pragma unroll
            for (int n = 0; n < 8; n++) {
                uint32_t b0 = sm.Ks[buf][n * 8 + g][kb + tg];
                uint32_t b1 = sm.Ks[buf][n * 8 + g][kb + tg + 4];
                mma_tf32(sc[0][n], a0, b0, b1);
                mma_tf32(sc[1][n], a1, b0, b1);
            }
        }

#pragma unroll
        for (int mb = 0; mb < 2; mb++) {
            const int rbase = w32 + mb * 16;
            const int rgA = qt0 + rbase + g;
            const int rgB = rgA + 8;
            const bool band = (s0 < qt0 + rbase + 20) && (s0 + 64 > qt0 + rbase - 4);

            if (band) {
#pragma unroll
                for (int n = 0; n < 8; n++) {
#pragma unroll
                    for (int e = 0; e < 2; e++) {
                        int col = s0 + n * 8 + tg * 2 + e;
                        int d0 = col - rgA + 4;
                        if ((unsigned)d0 <= 8u) sc[mb][n][e] += sm.qe[rbase + g][d0];
                        int d1 = col - rgB + 4;
                        if ((unsigned)d1 <= 8u) sc[mb][n][2 + e] += sm.qe[rbase + g + 8][d1];
                    }
                }
            }

#pragma unroll
            for (int n = 0; n < 8; n++) {
                float p0 = __uint_as_float(f2tf(ex2(sc[mb][n][0])));
                float p1 = __uint_as_float(f2tf(ex2(sc[mb][n][1])));
                float p2 = __uint_as_float(f2tf(ex2(sc[mb][n][2])));
                float p3 = __uint_as_float(f2tf(ex2(sc[mb][n][3])));
                sc[mb][n][0] = p0; sc[mb][n][1] = p1;
                sc[mb][n][2] = p2; sc[mb][n][3] = p3;
                lp[mb][0] += p0 + p1;
                lp[mb][1] += p2 + p3;
            }
            if (band) {
#pragma unroll
                for (int n = 0; n < 8; n++) {
#pragma unroll
                    for (int e = 0; e < 2; e++) {
                        int col = s0 + n * 8 + tg * 2 + e;
                        int d0 = col - rgA + 4;
                        if ((unsigned)d0 <= 8u) sm.band[rbase + g][d0] = sc[mb][n][e];
                        int d1 = col - rgB + 4;
                        if ((unsigned)d1 <= 8u) sm.band[rbase + g + 8][d1] = sc[mb][n][2 + e];
                    }
                }
                __syncwarp();
#pragma unroll
                for (int dd = 0; dd < 9; dd++) {
                    int sgA = rgA + dd - 4;
                    if (sgA >= s0 && sgA < s0 + 64) {
                        float p = sm.band[rbase + g][dd];
#pragma unroll
                        for (int n = 0; n < 8; n++) {
                            float2 e2 = *(const float2*)&sm.ev[dd][n * 8 + tg * 2];
                            of[mb][n][0] += p * e2.x;
                            of[mb][n][1] += p * e2.y;
                        }
                    }
                    int sgB = rgB + dd - 4;
                    if (sgB >= s0 && sgB < s0 + 64) {
                        float p = sm.band[rbase + g + 8][dd];
#pragma unroll
                        for (int n = 0; n < 8; n++) {
                            float2 e2 = *(const float2*)&sm.ev[dd][n * 8 + tg * 2];
                            of[mb][n][2] += p * e2.x;
                            of[mb][n][3] += p * e2.y;
                        }
                    }
                }
            }
        }

#pragma unroll
        for (int ks = 0; ks < 8; ks++) {
            uint32_t a[2][4];
#pragma unroll
            for (int mb = 0; mb < 2; mb++) {
                a[mb][0] = __float_as_uint(sc[mb][ks][0]);
                a[mb][1] = __float_as_uint(sc[mb][ks][2]);
                a[mb][2] = __float_as_uint(sc[mb][ks][1]);
                a[mb][3] = __float_as_uint(sc[mb][ks][3]);
            }
            int kb = ks * 8;
#pragma unroll
            for (int n = 0; n < 8; n++) {
                uint32_t b0 = sm.Vs[kb + tg][n * 8 + g];
                uint32_t b1 = sm.Vs[kb + tg + 4][n * 8 + g];
                mma_tf32(of[0][n], a[0], b0, b1);
                mma_tf32(of[1][n], a[1], b0, b1);
            }
        }
        __syncthreads();

        if (j < 15) {
            const int s1 = s0 + 64;
#pragma unroll
            for (int i = 0; i < 8; i++) {
                int idx = tid + i * 128;
                int r = idx >> 4, c4 = (idx & 15) << 2;
                cp16(&sm.Vs[vrow(r)][c4], &V[(size_t)(s1 + r) * D_SZ + c4]);
            }
            CP_COMMIT();
        }
    }

#pragma unroll
    for (int mb = 0; mb < 2; mb++) {
        float l0 = lp[mb][0], l1 = lp[mb][1];
        l0 += __shfl_xor_sync(0xffffffffu, l0, 1);
        l0 += __shfl_xor_sync(0xffffffffu, l0, 2);
        l1 += __shfl_xor_sync(0xffffffffu, l1, 1);
        l1 += __shfl_xor_sync(0xffffffffu, l1, 2);
        float li0 = 1.0f / l0, li1 = 1.0f / l1;
        int rgA = qt0 + w32 + mb * 16 + g;
        int rgB = rgA + 8;
        float* baseA = g_att + ((size_t)(b * T_SZ + rgA)) * C_SZ + h * D_SZ;
        float* baseB = g_att + ((size_t)(b * T_SZ + rgB)) * C_SZ + h * D_SZ;
#pragma unroll
        for (int n = 0; n < 8; n++) {
            int col = n * 8 + tg * 2;
            *(float2*)&baseA[col] =
                make_float2(of[mb][n][0] * li0, of[mb][n][1] * li0);
            *(float2*)&baseB[col] =
                make_float2(of[mb][n][2] * li1, of[mb][n][3] * li1);
        }
    }
}

// ---------------------------------------------------------------------------
// Launch
// ---------------------------------------------------------------------------
extern "C" void kernel_launch(void* const* d_in, const int* in_sizes, int n_in,
                              void* d_out, int out_size)
{
    const float* x    = (const float*)d_in[0];
    const float* c    = (const float*)d_in[1];
    const float* Wq   = (const float*)d_in[2];
    const float* bq   = (const float*)d_in[3];
    const float* Wk   = (const float*)d_in[4];
    const float* bk   = (const float*)d_in[5];
    const float* Wv   = (const float*)d_in[6];
    const float* bv   = (const float*)d_in[7];
    const float* Wo   = (const float*)d_in[8];
    const float* bo   = (const float*)d_in[9];
    const float* embk = (const float*)d_in[10];
    const float* embv = (const float*)d_in[11];
    float* out = (float*)d_out;

    (void)cudaFuncSetAttribute(attn_kernel,
                               cudaFuncAttributeMaxDynamicSharedMemorySize,
                               (int)sizeof(AttnSmem));
    (void)cudaFuncSetAttribute(gemm_qkv_kernel,
                               cudaFuncAttributeMaxDynamicSharedMemorySize,
                               (int)sizeof(GemmBigSmem));
    (void)cudaFuncSetAttribute(gemm_out_kernel,
                               cudaFuncAttributeMaxDynamicSharedMemorySize,
                               (int)sizeof(GemmSmem));

    prew_kernel<<<(4 * WGRP + 255) / 256, 256>>>(Wq, Wk, Wv, Wo);
    gemm_qkv_kernel<<<dim3(32, 12), 128, sizeof(GemmBigSmem)>>>(x, c, bq, bk, bv);
    attn_kernel<<<dim3(T_SZ / 128, H_SZ, B_SZ), 128, sizeof(AttnSmem)>>>(embk, embv);
    gemm_out_kernel<<<dim3(32, 8), 128, sizeof(GemmSmem)>>>(bo, out);
}

// round 14
// speedup vs baseline: 1.6420x; 1.0172x over previous
#include <cuda_runtime.h>
#include <cstdint>

#define B_SZ 4
#define T_SZ 1024
#define C_SZ 512
#define H_SZ 8
#define D_SZ 64

// Q pre-scale: 1/sqrt(64) * log2(e)  (softmax in exp2 domain)
#define Q_SCALE 0.18033688011112042f

__device__ float g_w[4][512 * 512];                // Wq*s, Wk, Wv, Wo (tf32)
__device__ float g_q[B_SZ * H_SZ * T_SZ * D_SZ];   // scaled + tf32
__device__ float g_k[B_SZ * H_SZ * T_SZ * D_SZ];   // tf32
__device__ float g_v[B_SZ * H_SZ * T_SZ * D_SZ];   // tf32
__device__ float g_att[B_SZ * T_SZ * C_SZ];

__device__ __forceinline__ uint32_t f2tf(float x) {
    uint32_t u;
    asm("cvt.rna.tf32.f32 %0, %1;" : "=r"(u) : "f"(x));
    return u;
}

__device__ __forceinline__ float ex2(float x) {
    float y;
    asm("ex2.approx.ftz.f32 %0, %1;" : "=f"(y) : "f"(x));
    return y;
}

__device__ __forceinline__ void mma_tf32(float c[4], const uint32_t a[4],
                                         uint32_t b0, uint32_t b1) {
    asm volatile(
        "mma.sync.aligned.m16n8k8.row.col.f32.tf32.tf32.f32 "
        "{%0,%1,%2,%3}, {%4,%5,%6,%7}, {%8,%9}, {%0,%1,%2,%3};\n"
        : "+f"(c[0]), "+f"(c[1]), "+f"(c[2]), "+f"(c[3])
        : "r"(a[0]), "r"(a[1]), "r"(a[2]), "r"(a[3]), "r"(b0), "r"(b1));
}

__device__ __forceinline__ void cp16(void* dst_smem, const void* src) {
    uint32_t d = (uint32_t)__cvta_generic_to_shared(dst_smem);
    asm volatile("cp.async.cg.shared.global [%0], [%1], 16;" :: "r"(d), "l"(src));
}
#define CP_COMMIT() asm volatile("cp.async.commit_group;" ::: "memory")

// ---------------------------------------------------------------------------
// Preconvert weights only: Wq*Q_SCALE, Wk, Wv, Wo -> tf32 in g_w.
// ---------------------------------------------------------------------------
#define WGRP (512 * 512 / 8)

__global__ __launch_bounds__(256) void prew_kernel(
    const float* __restrict__ Wq, const float* __restrict__ Wk,
    const float* __restrict__ Wv, const float* __restrict__ Wo)
{
    int gid = blockIdx.x * 256 + threadIdx.x;
    if (gid >= 4 * WGRP) return;
    int wi = gid / WGRP;
    int off = (gid - wi * WGRP) * 8;
    const float* src = (wi == 0) ? Wq : (wi == 1) ? Wk : (wi == 2) ? Wv : Wo;
    float s = (wi == 0) ? Q_SCALE : 1.0f;
    float4 f0 = *(const float4*)&src[off];
    float4 f1 = *(const float4*)&src[off + 4];
    *(uint4*)&g_w[wi][off] =
        make_uint4(f2tf(f0.x * s), f2tf(f0.y * s), f2tf(f0.z * s), f2tf(f0.w * s));
    *(uint4*)&g_w[wi][off + 4] =
        make_uint4(f2tf(f1.x * s), f2tf(f1.y * s), f2tf(f1.z * s), f2tf(f1.w * s));
}

// ---------------------------------------------------------------------------
// QKV GEMM (big tile): CTA 128x128, 128 threads, 4 warps (2x2), warp 64x64.
// grid (32, 12): sel = by>>2 (q/k/v), n0 = (by&3)*128.
// ---------------------------------------------------------------------------
struct GemmBigSmem {
    float As[2][128][36];    // raw f32 activations
    float Bs[2][32][136];    // tf32 bits (preconverted weights)
};

__global__ __launch_bounds__(128, 2) void gemm_qkv_kernel(
    const float* __restrict__ x, const float* __restrict__ cc,
    const float* __restrict__ bq, const float* __restrict__ bk,
    const float* __restrict__ bv)
{
    extern __shared__ char raw[];
    GemmBigSmem& sm = *reinterpret_cast<GemmBigSmem*>(raw);

    const int sel = blockIdx.y >> 2;
    const float* A = (sel == 0) ? x : cc;
    const float* W = g_w[sel];
    const float* bias = (sel == 0) ? bq : (sel == 1) ? bk : bv;
    const int n0 = (blockIdx.y & 3) * 128;
    const int m0 = blockIdx.x * 128;
    const int tid = threadIdx.x;
    const int lane = tid & 31;
    const int wid = tid >> 5;
    const int g = lane >> 2;
    const int tg = lane & 3;
    const int wm = wid >> 1;
    const int wn = wid & 1;

    auto issue_tile = [&](int kt, int bufi) {
        int kb = kt * 32;
#pragma unroll
        for (int i = 0; i < 8; i++) {
            int idx = tid + i * 128;            // 0..1023
            int r = idx >> 3;
            int kk = (idx & 7) << 2;
            cp16(&sm.As[bufi][r][kk], &A[(size_t)(m0 + r) * 512 + kb + kk]);
        }
#pragma unroll
        for (int i = 0; i < 8; i++) {
            int idx = tid + i * 128;            // 0..1023
            int kk = idx >> 5;                  // 0..31
            int nn = (idx & 31) << 2;           // 0..124
            cp16(&sm.Bs[bufi][kk][nn], &W[(size_t)(kb + kk) * 512 + n0 + nn]);
        }
        CP_COMMIT();
    };

    float c[4][8][4];
#pragma unroll
    for (int i = 0; i < 4; i++)
#pragma unroll
        for (int j = 0; j < 8; j++)
#pragma unroll
            for (int q = 0; q < 4; q++) c[i][j][q] = 0.f;

    issue_tile(0, 0);

    for (int kt = 0; kt < 16; kt++) {
        asm volatile("cp.async.wait_group 0;" ::: "memory");
        __syncthreads();
        if (kt < 15) issue_tile(kt + 1, (kt + 1) & 1);
        const float (*Af)[36] = sm.As[kt & 1];
        const float (*Bf)[136] = sm.Bs[kt & 1];

#pragma unroll
        for (int ks = 0; ks < 4; ks++) {
            int kb = ks * 8;
            uint32_t a[4][4], b[8][2];
#pragma unroll
            for (int i = 0; i < 4; i++) {
                int mr = wm * 64 + i * 16 + g;
                a[i][0] = f2tf(Af[mr][kb + tg]);
                a[i][1] = f2tf(Af[mr + 8][kb + tg]);
                a[i][2] = f2tf(Af[mr][kb + tg + 4]);
                a[i][3] = f2tf(Af[mr + 8][kb + tg + 4]);
            }
#pragma unroll
            for (int j = 0; j < 8; j++) {
                int nc = wn * 64 + j * 8 + g;
                b[j][0] = __float_as_uint(Bf[kb + tg][nc]);
                b[j][1] = __float_as_uint(Bf[kb + tg + 4][nc]);
            }
#pragma unroll
            for (int i = 0; i < 4; i++)
#pragma unroll
                for (int j = 0; j < 8; j++) mma_tf32(c[i][j], a[i], b[j][0], b[j][1]);
        }
    }

#pragma unroll
    for (int i = 0; i < 4; i++) {
        int r0 = m0 + wm * 64 + i * 16 + g;
#pragma unroll
        for (int j = 0; j < 8; j++) {
            int col0 = n0 + wn * 64 + j * 8 + tg * 2;
            float bv0 = bias[col0], bv1 = bias[col0 + 1];
            if (sel == 0) { bv0 *= Q_SCALE; bv1 *= Q_SCALE; }
            float v00 = __uint_as_float(f2tf(c[i][j][0] + bv0));
            float v01 = __uint_as_float(f2tf(c[i][j][1] + bv1));
            float v10 = __uint_as_float(f2tf(c[i][j][2] + bv0));
            float v11 = __uint_as_float(f2tf(c[i][j][3] + bv1));
            float* outb = (sel == 0) ? g_q : (sel == 1) ? g_k : g_v;
            int hh = col0 >> 6;
            int d = col0 & 63;
            {
                int bb = r0 >> 10, t = r0 & 1023;
                size_t base = ((((size_t)bb * H_SZ + hh) << 10) + t) * D_SZ + d;
                *(float2*)&outb[base] = make_float2(v00, v01);
            }
            {
                int r1 = r0 + 8;
                int bb = r1 >> 10, t = r1 & 1023;
                size_t base = ((((size_t)bb * H_SZ + hh) << 10) + t) * D_SZ + d;
                *(float2*)&outb[base] = make_float2(v10, v11);
            }
        }
    }
}

// ---------------------------------------------------------------------------
// Output GEMM: BM=64, BN=128, 128 threads, 4 warps (2x2), warp tile 32x64.
// 2.0 issue slots per MMA; 52KB smem -> 3 CTAs/SM. grid (64, 4).
// ---------------------------------------------------------------------------
struct GemmOutSmem {
    float As[2][64][36];    // g_att (f32 values, already tf32-rounded)
    float Bs[2][32][136];   // tf32 bits (preconverted Wo)
};

__global__ __launch_bounds__(128, 3) void gemm_out_kernel(
    const float* __restrict__ bo, float* __restrict__ out_ext)
{
    extern __shared__ char raw[];
    GemmOutSmem& sm = *reinterpret_cast<GemmOutSmem*>(raw);

    const float* A = g_att;
    const float* W = g_w[3];
    const int m0 = blockIdx.x * 64;
    const int n0 = blockIdx.y * 128;
    const int tid = threadIdx.x;
    const int lane = tid & 31;
    const int wid = tid >> 5;
    const int g = lane >> 2;
    const int tg = lane & 3;
    const int wm = wid >> 1;       // 0..1 -> 32-row half
    const int wn = wid & 1;        // 0..1 -> 64-col half

    auto issue_tile = [&](int kt, int bufi) {
        int kb = kt * 32;
#pragma unroll
        for (int i = 0; i < 4; i++) {
            int idx = tid + i * 128;            // 0..511
            int r = idx >> 3;                   // 0..63
            int kk = (idx & 7) << 2;
            cp16(&sm.As[bufi][r][kk], &A[(size_t)(m0 + r) * 512 + kb + kk]);
        }
#pragma unroll
        for (int i = 0; i < 8; i++) {
            int idx = tid + i * 128;            // 0..1023
            int kk = idx >> 5;                  // 0..31
            int nn = (idx & 31) << 2;           // 0..124
            cp16(&sm.Bs[bufi][kk][nn], &W[(size_t)(kb + kk) * 512 + n0 + nn]);
        }
        CP_COMMIT();
    };

    float c[2][8][4];
#pragma unroll
    for (int i = 0; i < 2; i++)
#pragma unroll
        for (int j = 0; j < 8; j++)
#pragma unroll
            for (int q = 0; q < 4; q++) c[i][j][q] = 0.f;

    issue_tile(0, 0);

    for (int kt = 0; kt < 16; kt++) {
        asm volatile("cp.async.wait_group 0;" ::: "memory");
        __syncthreads();
        if (kt < 15) issue_tile(kt + 1, (kt + 1) & 1);
        const float (*Af)[36] = sm.As[kt & 1];
        const float (*Bf)[136] = sm.Bs[kt & 1];

#pragma unroll
        for (int ks = 0; ks < 4; ks++) {
            int kb = ks * 8;
            uint32_t a[2][4], b[8][2];
#pragma unroll
            for (int i = 0; i < 2; i++) {
                int mr = wm * 32 + i * 16 + g;
                a[i][0] = f2tf(Af[mr][kb + tg]);
                a[i][1] = f2tf(Af[mr + 8][kb + tg]);
                a[i][2] = f2tf(Af[mr][kb + tg + 4]);
                a[i][3] = f2tf(Af[mr + 8][kb + tg + 4]);
            }
#pragma unroll
            for (int j = 0; j < 8; j++) {
                int nc = wn * 64 + j * 8 + g;
                b[j][0] = __float_as_uint(Bf[kb + tg][nc]);
                b[j][1] = __float_as_uint(Bf[kb + tg + 4][nc]);
            }
#pragma unroll
            for (int i = 0; i < 2; i++)
#pragma unroll
                for (int j = 0; j < 8; j++) mma_tf32(c[i][j], a[i], b[j][0], b[j][1]);
        }
    }

#pragma unroll
    for (int i = 0; i < 2; i++) {
        int r0 = m0 + wm * 32 + i * 16 + g;
#pragma unroll
        for (int j = 0; j < 8; j++) {
            int col0 = n0 + wn * 64 + j * 8 + tg * 2;
            float v00 = c[i][j][0] + bo[col0];
            float v01 = c[i][j][1] + bo[col0 + 1];
            float v10 = c[i][j][2] + bo[col0];
            float v11 = c[i][j][3] + bo[col0 + 1];
            *(float2*)&out_ext[(size_t)r0 * 512 + col0] = make_float2(v00, v01);
            *(float2*)&out_ext[(size_t)(r0 + 8) * 512 + col0] = make_float2(v10, v11);
        }
    }
}

// ---------------------------------------------------------------------------
// Flash attention v10 (unchanged): shuffle-free PV (sigma-permuted V rows) +
// Q fragments ks0-3 hoisted. No online rescale. 128-q CTA, m32 warps.
// ---------------------------------------------------------------------------
struct AttnSmem {
    uint32_t Qs[128][68];
    uint32_t Ks[2][64][68];
    uint32_t Vs[64][72];      // rows sigma-permuted within 8-groups
    float ek[9][64];
    float ev[9][64];
    float qe[128][12];
    float band[128][12];
};

__global__ __launch_bounds__(128, 2) void attn_kernel(const float* __restrict__ embk,
                                                      const float* __restrict__ embv)
{
    extern __shared__ char smem_raw[];
    AttnSmem& sm = *reinterpret_cast<AttnSmem*>(smem_raw);

    const int tid = threadIdx.x;
    const int lane = tid & 31;
    const int wid = tid >> 5;
    const int g = lane >> 2;
    const int tg = lane & 3;
    const int w32 = wid * 32;
    const int qt0 = blockIdx.x * 128;
    const int h = blockIdx.y;
    const int b = blockIdx.z;
    const size_t head_off = ((size_t)(b * H_SZ + h)) * T_SZ * D_SZ;
    const float* Q = g_q + head_off;
    const float* K = g_k + head_off;
    const float* V = g_v + head_off;

    for (int i = tid; i < 128 * 16; i += 128) {
        int r = i >> 4, c4 = (i & 15) << 2;
        *(uint4*)&sm.Qs[r][c4] = *(const uint4*)&Q[(size_t)(qt0 + r) * D_SZ + c4];
    }
    for (int i = tid; i < 9 * 64; i += 128) {
        sm.ek[0][i] = embk[i];
        sm.ev[0][i] = embv[i];
    }
    __syncthreads();

    for (int i = tid; i < 128 * 9; i += 128) {
        int t = i / 9, dd = i - t * 9;
        const float* qrow = (const float*)sm.Qs[t];
        float s = 0.f;
#pragma unroll
        for (int d = 0; d < 64; d += 4) {
            float4 q4 = *(const float4*)&qrow[d];
            float4 e4 = *(const float4*)&sm.ek[dd][d];
            s += q4.x * e4.x + q4.y * e4.y + q4.z * e4.z + q4.w * e4.w;
        }
        sm.qe[t][dd] = s;
    }

    auto vrow = [](int r) {
        return (r & 56) | ((r & 1) << 2) | ((r >> 1) & 3);
    };

#pragma unroll
    for (int i = 0; i < 8; i++) {
        int idx = tid + i * 128;
        int r = idx >> 4, c4 = (idx & 15) << 2;
        cp16(&sm.Ks[0][r][c4], &K[(size_t)r * D_SZ + c4]);
        cp16(&sm.Vs[vrow(r)][c4], &V[(size_t)r * D_SZ + c4]);
    }
    CP_COMMIT();
    __syncthreads();

    uint32_t qh[4][8];
#pragma unroll
    for (int ks = 0; ks < 4; ks++) {
        int kb = ks * 8;
        int r0 = w32 + g, r1 = w32 + 16 + g;
        qh[ks][0] = sm.Qs[r0][kb + tg];
        qh[ks][1] = sm.Qs[r0 + 8][kb + tg];
        qh[ks][2] = sm.Qs[r0][kb + tg + 4];
        qh[ks][3] = sm.Qs[r0 + 8][kb + tg + 4];
        qh[ks][4] = sm.Qs[r1][kb + tg];
        qh[ks][5] = sm.Qs[r1 + 8][kb + tg];
        qh[ks][6] = sm.Qs[r1][kb + tg + 4];
        qh[ks][7] = sm.Qs[r1 + 8][kb + tg + 4];
    }

    float of[2][8][4];
#pragma unroll
    for (int mb = 0; mb < 2; mb++)
#pragma unroll
        for (int n = 0; n < 8; n++)
#pragma unroll
            for (int q = 0; q < 4; q++) of[mb][n][q] = 0.f;
    float lp[2][2] = {{0.f, 0.f}, {0.f, 0.f}};

    for (int j = 0; j < 16; j++) {
        const int s0 = j * 64;
        if (j < 15) {
            const int s1 = s0 + 64;
#pragma unroll
            for (int i = 0; i < 8; i++) {
                int idx = tid + i * 128;
                int r = idx >> 4, c4 = (idx & 15) << 2;
                cp16(&sm.Ks[(j + 1) & 1][r][c4], &K[(size_t)(s1 + r) * D_SZ + c4]);
            }
            CP_COMMIT();
            asm volatile("cp.async.wait_group 1;" ::: "memory");
        } else {
            asm volatile("cp.async.wait_group 0;" ::: "memory");
        }
        __syncthreads();
        const int buf = j & 1;

        float sc[2][8][4];
#pragma unroll
        for (int mb = 0; mb < 2; mb++)
#pragma unroll
            for (int n = 0; n < 8; n++)
#pragma unroll
                for (int q = 0; q < 4; q++) sc[mb][n][q] = 0.f;
#pragma unroll
        for (int ks = 0; ks < 8; ks++) {
            int kb = ks * 8;
            uint32_t a0[4], a1[4];
            if (ks < 4) {
                a0[0] = qh[ks][0]; a0[1] = qh[ks][1];
                a0[2] = qh[ks][2]; a0[3] = qh[ks][3];
                a1[0] = qh[ks][4]; a1[1] = qh[ks][5];
                a1[2] = qh[ks][6]; a1[3] = qh[ks][7];
            } else {
                int r0 = w32 + g, r1 = w32 + 16 + g;
                a0[0] = sm.Qs[r0][kb + tg];
                a0[1] = sm.Qs[r0 + 8][kb + tg];
                a0[2] = sm.Qs[r0][kb + tg + 4];
                a0[3] = sm.Qs[r0 + 8][kb + tg + 4];
                a1[0] = sm.Qs[r1][kb + tg];
                a1[1] = sm.Qs[r1 + 8][kb + tg];
                a1[2] = sm.Qs[r1][kb + tg + 4];
                a1[3] = sm.Qs[r1 + 8][kb + tg + 4];
            }
#pragma unroll
            for (int n = 0; n < 8; n++) {
                uint32_t b0 = sm.Ks[buf][n * 8 + g][kb + tg];
                uint32_t b1 = sm.Ks[buf][n * 8 + g][kb + tg + 4];
                mma_tf32(sc[0][n], a0, b0, b1);
                mma_tf32(sc[1][n], a1, b0, b1);
            }
        }

#pragma unroll
        for (int mb = 0; mb < 2; mb++) {
            const int rbase = w32 + mb * 16;
            const int rgA = qt0 + rbase + g;
            const int rgB = rgA + 8;
            const bool band = (s0 < qt0 + rbase + 20) && (s0 + 64 > qt0 + rbase - 4);

            if (band) {
#pragma unroll
                for (int n = 0; n < 8; n++) {
#pragma unroll
                    for (int e = 0; e < 2; e++) {
                        int col = s0 + n * 8 + tg * 2 + e;
                        int d0 = col - rgA + 4;
                        if ((unsigned)d0 <= 8u) sc[mb][n][e] += sm.qe[rbase + g][d0];
                        int d1 = col - rgB + 4;
                        if ((unsigned)d1 <= 8u) sc[mb][n][2 + e] += sm.qe[rbase + g + 8][d1];
                    }
                }
            }

#pragma unroll
            for (int n = 0; n < 8; n++) {
                float p0 = __uint_as_float(f2tf(ex2(sc[mb][n][0])));
                float p1 = __uint_as_float(f2tf(ex2(sc[mb][n][1])));
                float p2 = __uint_as_float(f2tf(ex2(sc[mb][n][2])));
                float p3 = __uint_as_float(f2tf(ex2(sc[mb][n][3])));
                sc[mb][n][0] = p0; sc[mb][n][1] = p1;
                sc[mb][n][2] = p2; sc[mb][n][3] = p3;
                lp[mb][0] += p0 + p1;
                lp[mb][1] += p2 + p3;
            }
            if (band) {
#pragma unroll
                for (int n = 0; n < 8; n++) {
#pragma unroll
                    for (int e = 0; e < 2; e++) {
                        int col = s0 + n * 8 + tg * 2 + e;
                        int d0 = col - rgA + 4;
                        if ((unsigned)d0 <= 8u) sm.band[rbase + g][d0] = sc[mb][n][e];
                        int d1 = col - rgB + 4;
                        if ((unsigned)d1 <= 8u) sm.band[rbase + g + 8][d1] = sc[mb][n][2 + e];
                    }
                }
                __syncwarp();
#pragma unroll
                for (int dd = 0; dd < 9; dd++) {
                    int sgA = rgA + dd - 4;
                    if (sgA >= s0 && sgA < s0 + 64) {
                        float p = sm.band[rbase + g][dd];
#pragma unroll
                        for (int n = 0; n < 8; n++) {
                            float2 e2 = *(const float2*)&sm.ev[dd][n * 8 + tg * 2];
                            of[mb][n][0] += p * e2.x;
                            of[mb][n][1] += p * e2.y;
                        }
                    }
                    int sgB = rgB + dd - 4;
                    if (sgB >= s0 && sgB < s0 + 64) {
                        float p = sm.band[rbase + g + 8][dd];
#pragma unroll
                        for (int n = 0; n < 8; n++) {
                            float2 e2 = *(const float2*)&sm.ev[dd][n * 8 + tg * 2];
                            of[mb][n][2] += p * e2.x;
                            of[mb][n][3] += p * e2.y;
                        }
                    }
                }
            }
        }

#pragma unroll
        for (int ks = 0; ks < 8; ks++) {
            uint32_t a[2][4];
#pragma unroll
            for (int mb = 0; mb < 2; mb++) {
                a[mb][0] = __float_as_uint(sc[mb][ks][0]);
                a[mb][1] = __float_as_uint(sc[mb][ks][2]);
                a[mb][2] = __float_as_uint(sc[mb][ks][1]);
                a[mb][3] = __float_as_uint(sc[mb][ks][3]);
            }
            int kb = ks * 8;
#pragma unroll
            for (int n = 0; n < 8; n++) {
                uint32_t b0 = sm.Vs[kb + tg][n * 8 + g];
                uint32_t b1 = sm.Vs[kb + tg + 4][n * 8 + g];
                mma_tf32(of[0][n], a[0], b0, b1);
                mma_tf32(of[1][n], a[1], b0, b1);
            }
        }
        __syncthreads();

        if (j < 15) {
            const int s1 = s0 + 64;
#pragma unroll
            for (int i = 0; i < 8; i++) {
                int idx = tid + i * 128;
                int r = idx >> 4, c4 = (idx & 15) << 2;
                cp16(&sm.Vs[vrow(r)][c4], &V[(size_t)(s1 + r) * D_SZ + c4]);
            }
            CP_COMMIT();
        }
    }

#pragma unroll
    for (int mb = 0; mb < 2; mb++) {
        float l0 = lp[mb][0], l1 = lp[mb][1];
        l0 += __shfl_xor_sync(0xffffffffu, l0, 1);
        l0 += __shfl_xor_sync(0xffffffffu, l0, 2);
        l1 += __shfl_xor_sync(0xffffffffu, l1, 1);
        l1 += __shfl_xor_sync(0xffffffffu, l1, 2);
        float li0 = 1.0f / l0, li1 = 1.0f / l1;
        int rgA = qt0 + w32 + mb * 16 + g;
        int rgB = rgA + 8;
        float* baseA = g_att + ((size_t)(b * T_SZ + rgA)) * C_SZ + h * D_SZ;
        float* baseB = g_att + ((size_t)(b * T_SZ + rgB)) * C_SZ + h * D_SZ;
#pragma unroll
        for (int n = 0; n < 8; n++) {
            int col = n * 8 + tg * 2;
            *(float2*)&baseA[col] =
                make_float2(of[mb][n][0] * li0, of[mb][n][1] * li0);
            *(float2*)&baseB[col] =
                make_float2(of[mb][n][2] * li1, of[mb][n][3] * li1);
        }
    }
}

// ---------------------------------------------------------------------------
// Launch
// ---------------------------------------------------------------------------
extern "C" void kernel_launch(void* const* d_in, const int* in_sizes, int n_in,
                              void* d_out, int out_size)
{
    const float* x    = (const float*)d_in[0];
    const float* c    = (const float*)d_in[1];
    const float* Wq   = (const float*)d_in[2];
    const float* bq   = (const float*)d_in[3];
    const float* Wk   = (const float*)d_in[4];
    const float* bk   = (const float*)d_in[5];
    const float* Wv   = (const float*)d_in[6];
    const float* bv   = (const float*)d_in[7];
    const float* Wo   = (const float*)d_in[8];
    const float* bo   = (const float*)d_in[9];
    const float* embk = (const float*)d_in[10];
    const float* embv = (const float*)d_in[11];
    float* out = (float*)d_out;

    (void)cudaFuncSetAttribute(attn_kernel,
                               cudaFuncAttributeMaxDynamicSharedMemorySize,
                               (int)sizeof(AttnSmem));
    (void)cudaFuncSetAttribute(gemm_qkv_kernel,
                               cudaFuncAttributeMaxDynamicSharedMemorySize,
                               (int)sizeof(GemmBigSmem));
    (void)cudaFuncSetAttribute(gemm_out_kernel,
                               cudaFuncAttributeMaxDynamicSharedMemorySize,
                               (int)sizeof(GemmOutSmem));

    prew_kernel<<<(4 * WGRP + 255) / 256, 256>>>(Wq, Wk, Wv, Wo);
    gemm_qkv_kernel<<<dim3(32, 12), 128, sizeof(GemmBigSmem)>>>(x, c, bq, bk, bv);
    attn_kernel<<<dim3(T_SZ / 128, H_SZ, B_SZ), 128, sizeof(AttnSmem)>>>(embk, embv);
    gemm_out_kernel<<<dim3(64, 4), 128, sizeof(GemmOutSmem)>>>(bo, out);
}